// round 6
// baseline (speedup 1.0000x reference)
#include <cuda_runtime.h>
#include <math.h>

#define FULLMASK 0xffffffffu
typedef unsigned long long u64;

static constexpr int NL     = 2048;
static constexpr int NQ     = 16384;
static constexpr int NB     = 2;
static constexpr int H      = 64;
static constexpr int PH     = 256;
static constexpr int COUT   = 3;
static constexpr int KCAP   = 32;
static constexpr int CAP    = 160;
static constexpr int THREADS= 128;
static constexpr int WARPS  = 4;
static constexpr int NBLOCK = 592;   // 148 SMs x 4 CTAs

// decoded scratch (device global: allocation-free)
__device__ float g_dec[NB * NQ * H];   // 8 MB

// ---- main-kernel shared memory layout (float offsets) ----
static constexpr int OFF_W1    = 0;         // 4096  [64][64], j contiguous
static constexpr int OFF_W2    = 4096;      // 4096
static constexpr int OFF_WE0   = 8192;      // 256   [4][64]
static constexpr int OFF_BE0   = 8448;      // 64
static constexpr int OFF_BE1   = 8512;      // 64
static constexpr int OFF_BE2   = 8576;      // 64
static constexpr int OFF_WSW0  = 8640;      // 32
static constexpr int OFF_BSW0  = 8672;      // 16
static constexpr int OFF_WSW1  = 8688;      // 32
static constexpr int OFF_BSW1  = 8720;      // 2 (+6 pad)
static constexpr int OFF_CAND  = 8728;      // 4 warps x 160 u64 = 1280 floats (8B aligned)
static constexpr int SMEM_FLOATS = 10008;
static constexpr int SMEM_BYTES  = SMEM_FLOATS * 4;   // 40032 B -> 4 CTAs/SM

// ---------- f32x2 packed helpers ----------
__device__ __forceinline__ u64 pk2(float a, float b) {
    u64 r; asm("mov.b64 %0,{%1,%2};" : "=l"(r) : "f"(a), "f"(b)); return r;
}
__device__ __forceinline__ void upk2(u64 v, float& a, float& b) {
    asm("mov.b64 {%0,%1},%2;" : "=f"(a), "=f"(b) : "l"(v));
}
__device__ __forceinline__ u64 f2fma(u64 a, u64 b, u64 c) {
    u64 d; asm("fma.rn.f32x2 %0,%1,%2,%3;" : "=l"(d) : "l"(a), "l"(b), "l"(c)); return d;
}
__device__ __forceinline__ u64 f2mul(u64 a, u64 b) {
    u64 d; asm("mul.rn.f32x2 %0,%1,%2;" : "=l"(d) : "l"(a), "l"(b)); return d;
}
__device__ __forceinline__ u64 f2add(u64 a, u64 b) {
    u64 d; asm("add.rn.f32x2 %0,%1,%2;" : "=l"(d) : "l"(a), "l"(b)); return d;
}
__device__ __forceinline__ u64 wsum2(u64 v) {
#pragma unroll
    for (int off = 16; off > 0; off >>= 1)
        v = f2add(v, __shfl_xor_sync(FULLMASK, v, off));
    return v;
}
__device__ __forceinline__ unsigned redux_min_u32(unsigned v) {
    unsigned r; asm("redux.sync.min.u32 %0, %1, 0xffffffff;" : "=r"(r) : "r"(v)); return r;
}

// branch-free gelu: A&S 7.1.26 erf (|abs err| <= 1.5e-7)
__device__ __forceinline__ float gelu_f(float x) {
    float z = fabsf(x) * 0.7071067811865476f;
    float t = __fdividef(1.0f, fmaf(0.3275911f, z, 1.0f));
    float p = t * fmaf(t, fmaf(t, fmaf(t, fmaf(t, 1.061405429f, -1.453152027f),
                                        1.421413741f), -0.284496736f), 0.254829592f);
    float e = __expf(-z * z);
    float er = fmaf(-p, e, 1.0f);
    er = copysignf(er, x);
    return 0.5f * x * (1.0f + er);
}

__device__ __forceinline__ void ce(u64& a, u64& b) {
    u64 lo = a < b ? a : b;
    u64 hi = a < b ? b : a;
    a = lo; b = hi;
}

__global__ void __launch_bounds__(THREADS, 4)
magno_kernel(const float* __restrict__ lat,  const float* __restrict__ rnd,
             const float* __restrict__ qry,
             const float* __restrict__ we0,  const float* __restrict__ be0,
             const float* __restrict__ we1,  const float* __restrict__ be1,
             const float* __restrict__ we2,  const float* __restrict__ be2,
             const float* __restrict__ wsw0, const float* __restrict__ bsw0,
             const float* __restrict__ wsw1, const float* __restrict__ bsw1)
{
    extern __shared__ float sm[];
    const int tid = threadIdx.x;

    for (int t = tid; t < H*H;  t += THREADS) sm[OFF_W1+t]  = we1[t];
    for (int t = tid; t < H*H;  t += THREADS) sm[OFF_W2+t]  = we2[t];
    for (int t = tid; t < 4*H;  t += THREADS) sm[OFF_WE0+t] = we0[t];
    for (int t = tid; t < H;    t += THREADS) sm[OFF_BE0+t] = be0[t];
    for (int t = tid; t < H;    t += THREADS) sm[OFF_BE1+t] = be1[t];
    for (int t = tid; t < H;    t += THREADS) sm[OFF_BE2+t] = be2[t];
    if (tid < 32)              sm[OFF_WSW0+tid]    = wsw0[tid];
    if (tid < 16)              sm[OFF_BSW0+tid]    = bsw0[tid];
    if (tid >= 32 && tid < 64) sm[OFF_WSW1+tid-32] = wsw1[tid-32];
    if (tid >= 64 && tid < 66) sm[OFF_BSW1+tid-64] = bsw1[tid-64];
    __syncthreads();

    const int warp = tid >> 5, lane = tid & 31;
    u64* cand = (u64*)(sm + OFF_CAND) + warp * CAP;
    const float2* latf2 = (const float2*)lat;

    const float R0SQ = (float)(0.055 * 0.055);
    const float R1SQ = (float)(0.11  * 0.11);
    const unsigned lt_mask = (1u << lane) - 1u;

    for (int q = blockIdx.x * WARPS + warp; q < NB * NQ; q += gridDim.x * WARPS) {
        const int  bix = q >> 14;
        const float qx = qry[2*q], qy = qry[2*q+1];

        // ---- per-query scale-mixing weights ----
        float s0 = sm[OFF_BSW1+0], s1 = sm[OFF_BSW1+1];
#pragma unroll
        for (int t = 0; t < 16; t++) {
            float z = sm[OFF_BSW0+t] + qx*sm[OFF_WSW0+t] + qy*sm[OFF_WSW0+16+t];
            z = fmaxf(z, 0.0f);
            s0 = fmaf(z, sm[OFF_WSW1+2*t+0], s0);
            s1 = fmaf(z, sm[OFF_WSW1+2*t+1], s1);
        }
        float mx = fmaxf(s0, s1);
        float e0 = __expf(s0 - mx), e1 = __expf(s1 - mx);
        float inv = __fdividef(1.0f, e0 + e1);
        float sw0v = e0 * inv, sw1v = e1 * inv;

        // ---- radius-filtered candidate collection ----
        int cnt = 0;
        for (int l = lane; l < NL; l += 32) {
            float2 y = __ldg(latf2 + l);
            float dx = qx - y.x, dy = qy - y.y;
            float d2 = __fadd_rn(__fmul_rn(dx, dx), __fmul_rn(dy, dy));
            bool pr = d2 <= R1SQ;
            unsigned m = __ballot_sync(FULLMASK, pr);
            if (pr) {
                int pos = cnt + __popc(m & lt_mask);
                if (pos < CAP)
                    cand[pos] = ((u64)__float_as_uint(d2) << 32) | (unsigned)l;
            }
            cnt += __popc(m);
        }
        if (cnt > CAP) cnt = CAP;
        __syncwarp();

        // ---- exact K=32 smallest selection ----
        u64 mykey = 0x7f7fffff00000000ull;
        int nsel;
        if (cnt <= KCAP) {
            nsel = cnt;
            if (lane < cnt) mykey = cand[lane];
        } else {
            nsel = KCAP;
            u64 c0, c1, c2, c3, c4, c5;
            c0 = (lane       < cnt) ? cand[lane      ] : ~0ull;
            c1 = (lane + 32  < cnt) ? cand[lane + 32 ] : ~0ull;
            c2 = (lane + 64  < cnt) ? cand[lane + 64 ] : ~0ull;
            c3 = (lane + 96  < cnt) ? cand[lane + 96 ] : ~0ull;
            c4 = (lane + 128 < cnt) ? cand[lane + 128] : ~0ull;
            c5 = ~0ull;
            ce(c0,c1); ce(c2,c3); ce(c4,c5);
            ce(c0,c2); ce(c3,c5); ce(c1,c4);
            ce(c0,c1); ce(c2,c3); ce(c4,c5);
            ce(c1,c2); ce(c3,c4); ce(c2,c3);

            unsigned hdb = (unsigned)(c0 >> 32);
#pragma unroll 1
            for (int r = 0; r < KCAP; r++) {
                unsigned m = redux_min_u32(hdb);
                unsigned tied = __ballot_sync(FULLMASK, hdb == m);
                int src;
                if ((tied & (tied - 1u)) == 0u) {
                    src = __ffs(tied) - 1;
                } else {
                    unsigned lw = (hdb == m) ? (unsigned)c0 : 0xffffffffu;
                    unsigned mi = redux_min_u32(lw);
                    src = __ffs(__ballot_sync(FULLMASK, lw == mi)) - 1;
                }
                u64 win = __shfl_sync(FULLMASK, c0, src);
                if (lane == r) mykey = win;
                bool pop = (lane == src);
                c0 = pop ? c1 : c0;
                c1 = pop ? c2 : c1;
                c2 = pop ? c3 : c2;
                c3 = pop ? c4 : c3;
                c4 = pop ? c5 : c4;
                c5 = pop ? ~0ull : c5;
                hdb = (unsigned)(c0 >> 32);
            }
        }
        float seld2  = __uint_as_float((unsigned)(mykey >> 32));
        int   selidx = (int)(mykey & 0xffffffffu);
        if (lane >= nsel) { seld2 = 3.4e38f; selidx = 0; }

        bool v0 = (lane < nsel) && (seld2 <= R0SQ);
        int  c0cnt = __popc(__ballot_sync(FULLMASK, v0));
        float coeff = 0.0f;
        if (v0)          coeff += sw0v / (float)(c0cnt > 1 ? c0cnt : 1);
        if (lane < nsel) coeff += sw1v / (float)(nsel  > 1 ? nsel  : 1);

        const float* frowf = rnd + (size_t)(bix * NL + selidx) * H;
        asm volatile("prefetch.global.L1 [%0];" :: "l"(frowf));
        asm volatile("prefetch.global.L1 [%0];" :: "l"(frowf + 32));

        // ---- layer 0 ----
        float h0[64];
        {
            float2 yc = __ldg(latf2 + selidx);
            u64 yx2 = pk2(yc.x, yc.x), yy2 = pk2(yc.y, yc.y);
            u64 qx2 = pk2(qx, qx),     qy2 = pk2(qy, qy);
            const u64* w0r0 = (const u64*)(sm + OFF_WE0);
            const u64* w0r1 = (const u64*)(sm + OFF_WE0 + 64);
            const u64* w0r2 = (const u64*)(sm + OFF_WE0 + 128);
            const u64* w0r3 = (const u64*)(sm + OFF_WE0 + 192);
            const u64* b0p  = (const u64*)(sm + OFF_BE0);
#pragma unroll
            for (int jp = 0; jp < 32; jp++) {
                u64 t = b0p[jp];
                t = f2fma(yx2, w0r0[jp], t);
                t = f2fma(yy2, w0r1[jp], t);
                t = f2fma(qx2, w0r2[jp], t);
                t = f2fma(qy2, w0r3[jp], t);
                float a, b; upk2(t, a, b);
                h0[2*jp]   = gelu_f(a);
                h0[2*jp+1] = gelu_f(b);
            }
        }

        // ---- layer 1 (channel-tiled x2) ----
        float h1[64];
        {
            const ulonglong2* w1 = (const ulonglong2*)(sm + OFF_W1);
#pragma unroll
            for (int t = 0; t < 2; t++) {
                u64 a[16];
                const u64* b1p = (const u64*)(sm + OFF_BE1) + 8*t;
#pragma unroll
                for (int p = 0; p < 16; p++) a[p] = b1p[p];
#pragma unroll 4
                for (int i = 0; i < 64; i++) {
                    u64 hh = pk2(h0[i], h0[i]);
                    const ulonglong2* row = w1 + i*16 + t*8;
#pragma unroll
                    for (int j2 = 0; j2 < 8; j2++) {
                        ulonglong2 w = row[j2];
                        a[2*j2]   = f2fma(hh, w.x, a[2*j2]);
                        a[2*j2+1] = f2fma(hh, w.y, a[2*j2+1]);
                    }
                }
#pragma unroll
                for (int p = 0; p < 16; p++) {
                    float x, y; upk2(a[p], x, y);
                    h1[32*t + 2*p]   = gelu_f(x);
                    h1[32*t + 2*p+1] = gelu_f(y);
                }
            }
        }

        // ---- layer 2 + f(y)*coeff + neighbor-reduce -> decoded store ----
        u64 myd = 0;
        {
            u64 cc = pk2(coeff, coeff);
            const float4* frow = (const float4*)frowf;
            const ulonglong2* w2 = (const ulonglong2*)(sm + OFF_W2);
#pragma unroll
            for (int t = 0; t < 2; t++) {
                u64 a[16];
                const u64* b2p = (const u64*)(sm + OFF_BE2) + 8*t;
#pragma unroll
                for (int p = 0; p < 16; p++) a[p] = b2p[p];
#pragma unroll 4
                for (int i = 0; i < 64; i++) {
                    u64 hh = pk2(h1[i], h1[i]);
                    const ulonglong2* row = w2 + i*16 + t*8;
#pragma unroll
                    for (int j2 = 0; j2 < 8; j2++) {
                        ulonglong2 w = row[j2];
                        a[2*j2]   = f2fma(hh, w.x, a[2*j2]);
                        a[2*j2+1] = f2fma(hh, w.y, a[2*j2+1]);
                    }
                }
#pragma unroll
                for (int p2 = 0; p2 < 8; p2++) {
                    float4 f4 = __ldg(frow + 8*t + p2);
                    u64 rA = f2mul(a[2*p2],   f2mul(pk2(f4.x, f4.y), cc));
                    u64 rB = f2mul(a[2*p2+1], f2mul(pk2(f4.z, f4.w), cc));
                    rA = wsum2(rA);   // channels chb, chb+1 (all lanes)
                    rB = wsum2(rB);   // channels chb+2, chb+3
                    int lt = 16*t + 2*p2;       // lane owning (chb, chb+1)
                    if (lane == lt)     myd = rA;
                    if (lane == lt + 1) myd = rB;
                }
            }
        }
        // coalesced decoded store: lane l -> channels 2l, 2l+1
        ((u64*)g_dec)[(size_t)q * 32 + lane] = myd;
    }
}

// ======== projection kernel: decoded[64] -> gelu(PH=256) -> COUT=3 ========
static constexpr int PTHREADS = 128;
static constexpr int PGRID    = NB * NQ / PTHREADS;   // 256

__global__ void __launch_bounds__(PTHREADS)
proj_kernel(const float* __restrict__ wp0, const float* __restrict__ bp0,
            const float* __restrict__ wp1, const float* __restrict__ bp1,
            float* __restrict__ out)
{
    const int row = blockIdx.x * PTHREADS + threadIdx.x;

    // load decoded row into registers
    float dec[64];
    {
        const float4* dp = (const float4*)(g_dec + (size_t)row * H);
#pragma unroll
        for (int i = 0; i < 16; i++) {
            float4 v = dp[i];
            dec[4*i+0] = v.x; dec[4*i+1] = v.y;
            dec[4*i+2] = v.z; dec[4*i+3] = v.w;
        }
    }

    float o0 = __ldg(bp1 + 0), o1 = __ldg(bp1 + 1), o2 = __ldg(bp1 + 2);

#pragma unroll 1
    for (int ch = 0; ch < 4; ch++) {           // 4 chunks of 64 hidden
        u64 a[32];
        {
            const u64* bp = (const u64*)(bp0 + ch * 64);
#pragma unroll
            for (int p = 0; p < 32; p++) a[p] = __ldg(bp + p);
        }
#pragma unroll 4
        for (int i = 0; i < 64; i++) {
            u64 dd = pk2(dec[i], dec[i]);
            const float4* wr = (const float4*)(wp0 + (size_t)i * PH + ch * 64);
#pragma unroll
            for (int j4 = 0; j4 < 16; j4++) {
                float4 w = __ldg(wr + j4);     // warp-uniform broadcast, 1 wf
                a[2*j4]   = f2fma(dd, pk2(w.x, w.y), a[2*j4]);
                a[2*j4+1] = f2fma(dd, pk2(w.z, w.w), a[2*j4+1]);
            }
        }
#pragma unroll
        for (int p = 0; p < 32; p++) {
            float x, y; upk2(a[p], x, y);
            float g0 = gelu_f(x), g1 = gelu_f(y);
            int jj = ch * 64 + 2 * p;
            o0 = fmaf(g0, __ldg(wp1 + jj*3 + 0), o0);
            o1 = fmaf(g0, __ldg(wp1 + jj*3 + 1), o1);
            o2 = fmaf(g0, __ldg(wp1 + jj*3 + 2), o2);
            o0 = fmaf(g1, __ldg(wp1 + jj*3 + 3), o0);
            o1 = fmaf(g1, __ldg(wp1 + jj*3 + 4), o1);
            o2 = fmaf(g1, __ldg(wp1 + jj*3 + 5), o2);
        }
    }

    out[row*3 + 0] = o0;
    out[row*3 + 1] = o1;
    out[row*3 + 2] = o2;
}

extern "C" void kernel_launch(void* const* d_in, const int* in_sizes, int n_in,
                              void* d_out, int out_size) {
    const float* lat  = (const float*)d_in[0];
    const float* rnd  = (const float*)d_in[1];
    const float* qry  = (const float*)d_in[2];
    const float* we0  = (const float*)d_in[3];
    const float* be0  = (const float*)d_in[4];
    const float* we1  = (const float*)d_in[5];
    const float* be1  = (const float*)d_in[6];
    const float* we2  = (const float*)d_in[7];
    const float* be2  = (const float*)d_in[8];
    const float* wsw0 = (const float*)d_in[9];
    const float* bsw0 = (const float*)d_in[10];
    const float* wsw1 = (const float*)d_in[11];
    const float* bsw1 = (const float*)d_in[12];
    const float* wp0  = (const float*)d_in[13];
    const float* bp0  = (const float*)d_in[14];
    const float* wp1  = (const float*)d_in[15];
    const float* bp1  = (const float*)d_in[16];
    float* out = (float*)d_out;

    cudaFuncSetAttribute(magno_kernel, cudaFuncAttributeMaxDynamicSharedMemorySize, SMEM_BYTES);
    magno_kernel<<<NBLOCK, THREADS, SMEM_BYTES>>>(
        lat, rnd, qry, we0, be0, we1, be1, we2, be2,
        wsw0, bsw0, wsw1, bsw1);
    proj_kernel<<<PGRID, PTHREADS>>>(wp0, bp0, wp1, bp1, out);
}

// round 7
// speedup vs baseline: 1.1076x; 1.1076x over previous
#include <cuda_runtime.h>
#include <math.h>

#define FULLMASK 0xffffffffu
typedef unsigned long long u64;

static constexpr int NL     = 2048;
static constexpr int NQ     = 16384;
static constexpr int NB     = 2;
static constexpr int H      = 64;
static constexpr int PH     = 256;
static constexpr int COUT   = 3;
static constexpr int KCAP   = 32;
static constexpr int CAP    = 160;
static constexpr int THREADS= 128;
static constexpr int WARPS  = 4;
static constexpr int NBLOCK = 592;   // 148 SMs x 4 CTAs

// decoded scratch (device global: allocation-free)
__device__ float g_dec[NB * NQ * H];   // 8 MB

// ---- main-kernel shared memory layout (float offsets) ----
static constexpr int OFF_W1    = 0;         // 4096  [64][64], j contiguous
static constexpr int OFF_W2    = 4096;      // 4096
static constexpr int OFF_WE0   = 8192;      // 256   [4][64]
static constexpr int OFF_BE0   = 8448;      // 64
static constexpr int OFF_BE1   = 8512;      // 64
static constexpr int OFF_BE2   = 8576;      // 64
static constexpr int OFF_WSW0  = 8640;      // 32
static constexpr int OFF_BSW0  = 8672;      // 16
static constexpr int OFF_WSW1  = 8688;      // 32
static constexpr int OFF_BSW1  = 8720;      // 2 (+6 pad)
static constexpr int OFF_UNION = 8728;      // per-warp 1088 floats (=544 u64):
                                            //   cand (160 u64) / transpose scratch (16 rows x 33 u64)
static constexpr int UNION_U64_PER_WARP = 544;
static constexpr int SMEM_FLOATS = OFF_UNION + WARPS * 1088;   // 13080
static constexpr int SMEM_BYTES  = SMEM_FLOATS * 4;            // 52320 B -> 4 CTAs/SM

// ---------- f32x2 packed helpers ----------
__device__ __forceinline__ u64 pk2(float a, float b) {
    u64 r; asm("mov.b64 %0,{%1,%2};" : "=l"(r) : "f"(a), "f"(b)); return r;
}
__device__ __forceinline__ void upk2(u64 v, float& a, float& b) {
    asm("mov.b64 {%0,%1},%2;" : "=f"(a), "=f"(b) : "l"(v));
}
__device__ __forceinline__ u64 f2fma(u64 a, u64 b, u64 c) {
    u64 d; asm("fma.rn.f32x2 %0,%1,%2,%3;" : "=l"(d) : "l"(a), "l"(b), "l"(c)); return d;
}
__device__ __forceinline__ u64 f2mul(u64 a, u64 b) {
    u64 d; asm("mul.rn.f32x2 %0,%1,%2;" : "=l"(d) : "l"(a), "l"(b)); return d;
}
__device__ __forceinline__ u64 f2add(u64 a, u64 b) {
    u64 d; asm("add.rn.f32x2 %0,%1,%2;" : "=l"(d) : "l"(a), "l"(b)); return d;
}
__device__ __forceinline__ unsigned redux_min_u32(unsigned v) {
    unsigned r; asm("redux.sync.min.u32 %0, %1, 0xffffffff;" : "=r"(r) : "r"(v)); return r;
}

// branch-free gelu: A&S 7.1.26 erf (|abs err| <= 1.5e-7)
__device__ __forceinline__ float gelu_f(float x) {
    float z = fabsf(x) * 0.7071067811865476f;
    float t = __fdividef(1.0f, fmaf(0.3275911f, z, 1.0f));
    float p = t * fmaf(t, fmaf(t, fmaf(t, fmaf(t, 1.061405429f, -1.453152027f),
                                        1.421413741f), -0.284496736f), 0.254829592f);
    float e = __expf(-z * z);
    float er = fmaf(-p, e, 1.0f);
    er = copysignf(er, x);
    return 0.5f * x * (1.0f + er);
}

__device__ __forceinline__ void ce(u64& a, u64& b) {
    u64 lo = a < b ? a : b;
    u64 hi = a < b ? b : a;
    a = lo; b = hi;
}

__global__ void __launch_bounds__(THREADS, 4)
magno_kernel(const float* __restrict__ lat,  const float* __restrict__ rnd,
             const float* __restrict__ qry,
             const float* __restrict__ we0,  const float* __restrict__ be0,
             const float* __restrict__ we1,  const float* __restrict__ be1,
             const float* __restrict__ we2,  const float* __restrict__ be2,
             const float* __restrict__ wsw0, const float* __restrict__ bsw0,
             const float* __restrict__ wsw1, const float* __restrict__ bsw1)
{
    extern __shared__ float sm[];
    const int tid = threadIdx.x;

    for (int t = tid; t < H*H;  t += THREADS) sm[OFF_W1+t]  = we1[t];
    for (int t = tid; t < H*H;  t += THREADS) sm[OFF_W2+t]  = we2[t];
    for (int t = tid; t < 4*H;  t += THREADS) sm[OFF_WE0+t] = we0[t];
    for (int t = tid; t < H;    t += THREADS) sm[OFF_BE0+t] = be0[t];
    for (int t = tid; t < H;    t += THREADS) sm[OFF_BE1+t] = be1[t];
    for (int t = tid; t < H;    t += THREADS) sm[OFF_BE2+t] = be2[t];
    if (tid < 32)              sm[OFF_WSW0+tid]    = wsw0[tid];
    if (tid < 16)              sm[OFF_BSW0+tid]    = bsw0[tid];
    if (tid >= 32 && tid < 64) sm[OFF_WSW1+tid-32] = wsw1[tid-32];
    if (tid >= 64 && tid < 66) sm[OFF_BSW1+tid-64] = bsw1[tid-64];
    __syncthreads();

    const int warp = tid >> 5, lane = tid & 31;
    u64* uptr = (u64*)(sm + OFF_UNION) + warp * UNION_U64_PER_WARP;
    u64* cand  = uptr;          // selection phase
    u64* trans = uptr;          // reduce phase (16 rows x 33 u64, padded)
    const float2* latf2 = (const float2*)lat;

    const float R0SQ = (float)(0.055 * 0.055);
    const float R1SQ = (float)(0.11  * 0.11);
    const unsigned lt_mask = (1u << lane) - 1u;

    for (int q = blockIdx.x * WARPS + warp; q < NB * NQ; q += gridDim.x * WARPS) {
        const int  bix = q >> 14;
        const float qx = qry[2*q], qy = qry[2*q+1];

        // ---- per-query scale-mixing weights ----
        float s0 = sm[OFF_BSW1+0], s1 = sm[OFF_BSW1+1];
#pragma unroll
        for (int t = 0; t < 16; t++) {
            float z = sm[OFF_BSW0+t] + qx*sm[OFF_WSW0+t] + qy*sm[OFF_WSW0+16+t];
            z = fmaxf(z, 0.0f);
            s0 = fmaf(z, sm[OFF_WSW1+2*t+0], s0);
            s1 = fmaf(z, sm[OFF_WSW1+2*t+1], s1);
        }
        float mx = fmaxf(s0, s1);
        float e0 = __expf(s0 - mx), e1 = __expf(s1 - mx);
        float inv = __fdividef(1.0f, e0 + e1);
        float sw0v = e0 * inv, sw1v = e1 * inv;

        // ---- radius-filtered candidate collection ----
        int cnt = 0;
        for (int l = lane; l < NL; l += 32) {
            float2 y = __ldg(latf2 + l);
            float dx = qx - y.x, dy = qy - y.y;
            float d2 = __fadd_rn(__fmul_rn(dx, dx), __fmul_rn(dy, dy));
            bool pr = d2 <= R1SQ;
            unsigned m = __ballot_sync(FULLMASK, pr);
            if (pr) {
                int pos = cnt + __popc(m & lt_mask);
                if (pos < CAP)
                    cand[pos] = ((u64)__float_as_uint(d2) << 32) | (unsigned)l;
            }
            cnt += __popc(m);
        }
        if (cnt > CAP) cnt = CAP;
        __syncwarp();

        // ---- exact K=32 smallest selection ----
        u64 mykey = 0x7f7fffff00000000ull;
        int nsel;
        if (cnt <= KCAP) {
            nsel = cnt;
            if (lane < cnt) mykey = cand[lane];
        } else {
            nsel = KCAP;
            u64 c0, c1, c2, c3, c4, c5;
            c0 = (lane       < cnt) ? cand[lane      ] : ~0ull;
            c1 = (lane + 32  < cnt) ? cand[lane + 32 ] : ~0ull;
            c2 = (lane + 64  < cnt) ? cand[lane + 64 ] : ~0ull;
            c3 = (lane + 96  < cnt) ? cand[lane + 96 ] : ~0ull;
            c4 = (lane + 128 < cnt) ? cand[lane + 128] : ~0ull;
            c5 = ~0ull;
            ce(c0,c1); ce(c2,c3); ce(c4,c5);
            ce(c0,c2); ce(c3,c5); ce(c1,c4);
            ce(c0,c1); ce(c2,c3); ce(c4,c5);
            ce(c1,c2); ce(c3,c4); ce(c2,c3);

            unsigned hdb = (unsigned)(c0 >> 32);
#pragma unroll 1
            for (int r = 0; r < KCAP; r++) {
                unsigned m = redux_min_u32(hdb);
                unsigned tied = __ballot_sync(FULLMASK, hdb == m);
                int src;
                if ((tied & (tied - 1u)) == 0u) {
                    src = __ffs(tied) - 1;
                } else {
                    unsigned lw = (hdb == m) ? (unsigned)c0 : 0xffffffffu;
                    unsigned mi = redux_min_u32(lw);
                    src = __ffs(__ballot_sync(FULLMASK, lw == mi)) - 1;
                }
                u64 win = __shfl_sync(FULLMASK, c0, src);
                if (lane == r) mykey = win;
                bool pop = (lane == src);
                c0 = pop ? c1 : c0;
                c1 = pop ? c2 : c1;
                c2 = pop ? c3 : c2;
                c3 = pop ? c4 : c3;
                c4 = pop ? c5 : c4;
                c5 = pop ? ~0ull : c5;
                hdb = (unsigned)(c0 >> 32);
            }
        }
        float seld2  = __uint_as_float((unsigned)(mykey >> 32));
        int   selidx = (int)(mykey & 0xffffffffu);
        if (lane >= nsel) { seld2 = 3.4e38f; selidx = 0; }

        bool v0 = (lane < nsel) && (seld2 <= R0SQ);
        int  c0cnt = __popc(__ballot_sync(FULLMASK, v0));
        float coeff = 0.0f;
        if (v0)          coeff += sw0v / (float)(c0cnt > 1 ? c0cnt : 1);
        if (lane < nsel) coeff += sw1v / (float)(nsel  > 1 ? nsel  : 1);

        const float* frowf = rnd + (size_t)(bix * NL + selidx) * H;
        asm volatile("prefetch.global.L1 [%0];" :: "l"(frowf));
        asm volatile("prefetch.global.L1 [%0];" :: "l"(frowf + 32));

        // ---- layer 0 ----
        float h0[64];
        {
            float2 yc = __ldg(latf2 + selidx);
            u64 yx2 = pk2(yc.x, yc.x), yy2 = pk2(yc.y, yc.y);
            u64 qx2 = pk2(qx, qx),     qy2 = pk2(qy, qy);
            const u64* w0r0 = (const u64*)(sm + OFF_WE0);
            const u64* w0r1 = (const u64*)(sm + OFF_WE0 + 64);
            const u64* w0r2 = (const u64*)(sm + OFF_WE0 + 128);
            const u64* w0r3 = (const u64*)(sm + OFF_WE0 + 192);
            const u64* b0p  = (const u64*)(sm + OFF_BE0);
#pragma unroll
            for (int jp = 0; jp < 32; jp++) {
                u64 t = b0p[jp];
                t = f2fma(yx2, w0r0[jp], t);
                t = f2fma(yy2, w0r1[jp], t);
                t = f2fma(qx2, w0r2[jp], t);
                t = f2fma(qy2, w0r3[jp], t);
                float a, b; upk2(t, a, b);
                h0[2*jp]   = gelu_f(a);
                h0[2*jp+1] = gelu_f(b);
            }
        }

        // ---- layer 1 (channel-tiled x2) ----
        float h1[64];
        {
            const ulonglong2* w1 = (const ulonglong2*)(sm + OFF_W1);
#pragma unroll
            for (int t = 0; t < 2; t++) {
                u64 a[16];
                const u64* b1p = (const u64*)(sm + OFF_BE1) + 8*t;
#pragma unroll
                for (int p = 0; p < 16; p++) a[p] = b1p[p];
#pragma unroll 4
                for (int i = 0; i < 64; i++) {
                    u64 hh = pk2(h0[i], h0[i]);
                    const ulonglong2* row = w1 + i*16 + t*8;
#pragma unroll
                    for (int j2 = 0; j2 < 8; j2++) {
                        ulonglong2 w = row[j2];
                        a[2*j2]   = f2fma(hh, w.x, a[2*j2]);
                        a[2*j2+1] = f2fma(hh, w.y, a[2*j2+1]);
                    }
                }
#pragma unroll
                for (int p = 0; p < 16; p++) {
                    float x, y; upk2(a[p], x, y);
                    h1[32*t + 2*p]   = gelu_f(x);
                    h1[32*t + 2*p+1] = gelu_f(y);
                }
            }
        }

        // ---- layer 2 + f(y)*coeff + transpose-reduce over neighbors ----
        u64 myd = 0;
        {
            u64 cc = pk2(coeff, coeff);
            const float4* frow = (const float4*)frowf;
            const ulonglong2* w2 = (const ulonglong2*)(sm + OFF_W2);
#pragma unroll
            for (int t = 0; t < 2; t++) {
                u64 a[16];
                const u64* b2p = (const u64*)(sm + OFF_BE2) + 8*t;
#pragma unroll
                for (int p = 0; p < 16; p++) a[p] = b2p[p];
#pragma unroll 4
                for (int i = 0; i < 64; i++) {
                    u64 hh = pk2(h1[i], h1[i]);
                    const ulonglong2* row = w2 + i*16 + t*8;
#pragma unroll
                    for (int j2 = 0; j2 < 8; j2++) {
                        ulonglong2 w = row[j2];
                        a[2*j2]   = f2fma(hh, w.x, a[2*j2]);
                        a[2*j2+1] = f2fma(hh, w.y, a[2*j2+1]);
                    }
                }
                // weight by f(y)*coeff (a[p] = channels (32t+2p, 32t+2p+1))
#pragma unroll
                for (int p2 = 0; p2 < 8; p2++) {
                    float4 f4 = __ldg(frow + 8*t + p2);
                    a[2*p2]   = f2mul(a[2*p2],   f2mul(pk2(f4.x, f4.y), cc));
                    a[2*p2+1] = f2mul(a[2*p2+1], f2mul(pk2(f4.z, f4.w), cc));
                }
                // transpose via SMEM: scratch[p][lane], row stride 33 u64
                __syncwarp();   // prior-phase scratch reads complete
#pragma unroll
                for (int p = 0; p < 16; p++) trans[p*33 + lane] = a[p];
                __syncwarp();
                // lane l sums channel-pair (2l,2l+1); pair index l in [16t,16t+16)
                {
                    int p = lane & 15;
                    const u64* col = trans + p*33;
                    u64 s0 = 0, s1 = 0, s2 = 0, s3 = 0;
#pragma unroll
                    for (int k = 0; k < 8; k++) {
                        s0 = f2add(s0, col[4*k+0]);
                        s1 = f2add(s1, col[4*k+1]);
                        s2 = f2add(s2, col[4*k+2]);
                        s3 = f2add(s3, col[4*k+3]);
                    }
                    u64 tot = f2add(f2add(s0, s1), f2add(s2, s3));
                    if ((lane >> 4) == t) myd = tot;
                }
            }
        }
        // coalesced decoded store: lane l -> channels 2l, 2l+1
        ((u64*)g_dec)[(size_t)q * 32 + lane] = myd;
    }
}

// ======== projection kernel: decoded[64] -> gelu(PH=256) -> COUT=3 ========
static constexpr int PTHREADS = 128;
static constexpr int PGRID    = NB * NQ / PTHREADS;   // 256

// proj smem layout (floats)
static constexpr int POFF_WP0 = 0;          // 16384  [64][256]
static constexpr int POFF_BP0 = 16384;      // 256
static constexpr int POFF_WP1 = 16640;      // 768    [256][3]
static constexpr int POFF_BP1 = 17408;      // 3 (+1 pad)
static constexpr int PSMEM_FLOATS = 17412;
static constexpr int PSMEM_BYTES  = PSMEM_FLOATS * 4;   // 69648 B

__global__ void __launch_bounds__(PTHREADS)
proj_kernel(const float* __restrict__ wp0, const float* __restrict__ bp0,
            const float* __restrict__ wp1, const float* __restrict__ bp1,
            float* __restrict__ out)
{
    extern __shared__ float psm[];
    const int tid = threadIdx.x;
    for (int t = tid; t < H*PH;    t += PTHREADS) psm[POFF_WP0+t] = wp0[t];
    for (int t = tid; t < PH;      t += PTHREADS) psm[POFF_BP0+t] = bp0[t];
    for (int t = tid; t < PH*COUT; t += PTHREADS) psm[POFF_WP1+t] = wp1[t];
    if (tid < COUT) psm[POFF_BP1+tid] = bp1[tid];
    __syncthreads();

    const int row = blockIdx.x * PTHREADS + tid;

    // decoded row in registers
    float dec[64];
    {
        const float4* dp = (const float4*)(g_dec + (size_t)row * H);
#pragma unroll
        for (int i = 0; i < 16; i++) {
            float4 v = dp[i];
            dec[4*i+0] = v.x; dec[4*i+1] = v.y;
            dec[4*i+2] = v.z; dec[4*i+3] = v.w;
        }
    }

    float o0 = psm[POFF_BP1+0], o1 = psm[POFF_BP1+1], o2 = psm[POFF_BP1+2];

#pragma unroll 1
    for (int ch = 0; ch < 4; ch++) {           // 4 chunks of 64 hidden
        u64 a[32];
        {
            const u64* bp = (const u64*)(psm + POFF_BP0 + ch * 64);
#pragma unroll
            for (int p = 0; p < 32; p++) a[p] = bp[p];
        }
#pragma unroll 4
        for (int i = 0; i < 64; i++) {
            u64 dd = pk2(dec[i], dec[i]);
            const ulonglong2* wr =
                (const ulonglong2*)(psm + POFF_WP0 + (size_t)i * PH + ch * 64);
#pragma unroll
            for (int j2 = 0; j2 < 16; j2++) {
                ulonglong2 w = wr[j2];          // LDS.128 broadcast
                a[2*j2]   = f2fma(dd, w.x, a[2*j2]);
                a[2*j2+1] = f2fma(dd, w.y, a[2*j2+1]);
            }
        }
#pragma unroll
        for (int p = 0; p < 32; p++) {
            float x, y; upk2(a[p], x, y);
            float g0 = gelu_f(x), g1 = gelu_f(y);
            int jj = ch * 64 + 2 * p;
            o0 = fmaf(g0, psm[POFF_WP1 + jj*3 + 0], o0);
            o1 = fmaf(g0, psm[POFF_WP1 + jj*3 + 1], o1);
            o2 = fmaf(g0, psm[POFF_WP1 + jj*3 + 2], o2);
            o0 = fmaf(g1, psm[POFF_WP1 + jj*3 + 3], o0);
            o1 = fmaf(g1, psm[POFF_WP1 + jj*3 + 4], o1);
            o2 = fmaf(g1, psm[POFF_WP1 + jj*3 + 5], o2);
        }
    }

    out[row*3 + 0] = o0;
    out[row*3 + 1] = o1;
    out[row*3 + 2] = o2;
}

extern "C" void kernel_launch(void* const* d_in, const int* in_sizes, int n_in,
                              void* d_out, int out_size) {
    const float* lat  = (const float*)d_in[0];
    const float* rnd  = (const float*)d_in[1];
    const float* qry  = (const float*)d_in[2];
    const float* we0  = (const float*)d_in[3];
    const float* be0  = (const float*)d_in[4];
    const float* we1  = (const float*)d_in[5];
    const float* be1  = (const float*)d_in[6];
    const float* we2  = (const float*)d_in[7];
    const float* be2  = (const float*)d_in[8];
    const float* wsw0 = (const float*)d_in[9];
    const float* bsw0 = (const float*)d_in[10];
    const float* wsw1 = (const float*)d_in[11];
    const float* bsw1 = (const float*)d_in[12];
    const float* wp0  = (const float*)d_in[13];
    const float* bp0  = (const float*)d_in[14];
    const float* wp1  = (const float*)d_in[15];
    const float* bp1  = (const float*)d_in[16];
    float* out = (float*)d_out;

    cudaFuncSetAttribute(magno_kernel, cudaFuncAttributeMaxDynamicSharedMemorySize, SMEM_BYTES);
    cudaFuncSetAttribute(proj_kernel,  cudaFuncAttributeMaxDynamicSharedMemorySize, PSMEM_BYTES);
    magno_kernel<<<NBLOCK, THREADS, SMEM_BYTES>>>(
        lat, rnd, qry, we0, be0, we1, be1, we2, be2,
        wsw0, bsw0, wsw1, bsw1);
    proj_kernel<<<PGRID, PTHREADS, PSMEM_BYTES>>>(wp0, bp0, wp1, bp1, out);
}

// round 8
// speedup vs baseline: 1.1642x; 1.0511x over previous
#include <cuda_runtime.h>
#include <math.h>

#define FULLMASK 0xffffffffu
typedef unsigned long long u64;

static constexpr int NL     = 2048;
static constexpr int NQ     = 16384;
static constexpr int NB     = 2;
static constexpr int H      = 64;
static constexpr int PH     = 256;
static constexpr int COUT   = 3;
static constexpr int KCAP   = 32;
static constexpr int CAP    = 160;
static constexpr int THREADS= 128;
static constexpr int WARPS  = 4;
static constexpr int NBLOCK = 592;   // 148 SMs x 4 CTAs

// decoded scratch (device global: allocation-free)
__device__ float g_dec[NB * NQ * H];   // 8 MB

// ---- main-kernel shared memory layout (float offsets) ----
static constexpr int OFF_W1    = 0;         // 4096  [64][64], j contiguous
static constexpr int OFF_W2    = 4096;      // 4096
static constexpr int OFF_WE0   = 8192;      // 256   [4][64]
static constexpr int OFF_BE0   = 8448;      // 64
static constexpr int OFF_BE1   = 8512;      // 64
static constexpr int OFF_BE2   = 8576;      // 64
static constexpr int OFF_WSW0  = 8640;      // 32
static constexpr int OFF_BSW0  = 8672;      // 16
static constexpr int OFF_WSW1  = 8688;      // 32
static constexpr int OFF_BSW1  = 8720;      // 2 (+6 pad)
static constexpr int OFF_CAND  = 8728;      // 4 warps x 160 u64 = 1280 floats
static constexpr int SMEM_FLOATS = 10008;
static constexpr int SMEM_BYTES  = SMEM_FLOATS * 4;   // 40032 B -> 4 CTAs/SM, 68KB L1D left

// ---------- f32x2 packed helpers ----------
__device__ __forceinline__ u64 pk2(float a, float b) {
    u64 r; asm("mov.b64 %0,{%1,%2};" : "=l"(r) : "f"(a), "f"(b)); return r;
}
__device__ __forceinline__ void upk2(u64 v, float& a, float& b) {
    asm("mov.b64 {%0,%1},%2;" : "=f"(a), "=f"(b) : "l"(v));
}
__device__ __forceinline__ u64 f2fma(u64 a, u64 b, u64 c) {
    u64 d; asm("fma.rn.f32x2 %0,%1,%2,%3;" : "=l"(d) : "l"(a), "l"(b), "l"(c)); return d;
}
__device__ __forceinline__ u64 f2mul(u64 a, u64 b) {
    u64 d; asm("mul.rn.f32x2 %0,%1,%2;" : "=l"(d) : "l"(a), "l"(b)); return d;
}
__device__ __forceinline__ u64 f2add(u64 a, u64 b) {
    u64 d; asm("add.rn.f32x2 %0,%1,%2;" : "=l"(d) : "l"(a), "l"(b)); return d;
}
__device__ __forceinline__ unsigned redux_min_u32(unsigned v) {
    unsigned r; asm("redux.sync.min.u32 %0, %1, 0xffffffff;" : "=r"(r) : "r"(v)); return r;
}

// branch-free gelu: A&S 7.1.26 erf (|abs err| <= 1.5e-7)
__device__ __forceinline__ float gelu_f(float x) {
    float z = fabsf(x) * 0.7071067811865476f;
    float t = __fdividef(1.0f, fmaf(0.3275911f, z, 1.0f));
    float p = t * fmaf(t, fmaf(t, fmaf(t, fmaf(t, 1.061405429f, -1.453152027f),
                                        1.421413741f), -0.284496736f), 0.254829592f);
    float e = __expf(-z * z);
    float er = fmaf(-p, e, 1.0f);
    er = copysignf(er, x);
    return 0.5f * x * (1.0f + er);
}

__device__ __forceinline__ void ce(u64& a, u64& b) {
    u64 lo = a < b ? a : b;
    u64 hi = a < b ? b : a;
    a = lo; b = hi;
}

__global__ void __launch_bounds__(THREADS, 4)
magno_kernel(const float* __restrict__ lat,  const float* __restrict__ rnd,
             const float* __restrict__ qry,
             const float* __restrict__ we0,  const float* __restrict__ be0,
             const float* __restrict__ we1,  const float* __restrict__ be1,
             const float* __restrict__ we2,  const float* __restrict__ be2,
             const float* __restrict__ wsw0, const float* __restrict__ bsw0,
             const float* __restrict__ wsw1, const float* __restrict__ bsw1)
{
    extern __shared__ float sm[];
    const int tid = threadIdx.x;

    for (int t = tid; t < H*H;  t += THREADS) sm[OFF_W1+t]  = we1[t];
    for (int t = tid; t < H*H;  t += THREADS) sm[OFF_W2+t]  = we2[t];
    for (int t = tid; t < 4*H;  t += THREADS) sm[OFF_WE0+t] = we0[t];
    for (int t = tid; t < H;    t += THREADS) sm[OFF_BE0+t] = be0[t];
    for (int t = tid; t < H;    t += THREADS) sm[OFF_BE1+t] = be1[t];
    for (int t = tid; t < H;    t += THREADS) sm[OFF_BE2+t] = be2[t];
    if (tid < 32)              sm[OFF_WSW0+tid]    = wsw0[tid];
    if (tid < 16)              sm[OFF_BSW0+tid]    = bsw0[tid];
    if (tid >= 32 && tid < 64) sm[OFF_WSW1+tid-32] = wsw1[tid-32];
    if (tid >= 64 && tid < 66) sm[OFF_BSW1+tid-64] = bsw1[tid-64];
    __syncthreads();

    const int warp = tid >> 5, lane = tid & 31;
    u64* cand = (u64*)(sm + OFF_CAND) + warp * CAP;
    const float2* latf2 = (const float2*)lat;

    const float R0SQ = (float)(0.055 * 0.055);
    const float R1SQ = (float)(0.11  * 0.11);
    const unsigned lt_mask = (1u << lane) - 1u;

    for (int q = blockIdx.x * WARPS + warp; q < NB * NQ; q += gridDim.x * WARPS) {
        const int  bix = q >> 14;
        const float qx = qry[2*q], qy = qry[2*q+1];

        // ---- per-query scale-mixing weights ----
        float s0 = sm[OFF_BSW1+0], s1 = sm[OFF_BSW1+1];
#pragma unroll
        for (int t = 0; t < 16; t++) {
            float z = sm[OFF_BSW0+t] + qx*sm[OFF_WSW0+t] + qy*sm[OFF_WSW0+16+t];
            z = fmaxf(z, 0.0f);
            s0 = fmaf(z, sm[OFF_WSW1+2*t+0], s0);
            s1 = fmaf(z, sm[OFF_WSW1+2*t+1], s1);
        }
        float mx = fmaxf(s0, s1);
        float e0 = __expf(s0 - mx), e1 = __expf(s1 - mx);
        float inv = __fdividef(1.0f, e0 + e1);
        float sw0v = e0 * inv, sw1v = e1 * inv;

        // ---- radius-filtered candidate collection ----
        int cnt = 0;
        for (int l = lane; l < NL; l += 32) {
            float2 y = __ldg(latf2 + l);
            float dx = qx - y.x, dy = qy - y.y;
            float d2 = __fadd_rn(__fmul_rn(dx, dx), __fmul_rn(dy, dy));
            bool pr = d2 <= R1SQ;
            unsigned m = __ballot_sync(FULLMASK, pr);
            if (pr) {
                int pos = cnt + __popc(m & lt_mask);
                if (pos < CAP)
                    cand[pos] = ((u64)__float_as_uint(d2) << 32) | (unsigned)l;
            }
            cnt += __popc(m);
        }
        if (cnt > CAP) cnt = CAP;
        __syncwarp();

        // ---- exact K=32 smallest selection ----
        u64 mykey = 0x7f7fffff00000000ull;
        int nsel;
        if (cnt <= KCAP) {
            nsel = cnt;
            if (lane < cnt) mykey = cand[lane];
        } else {
            nsel = KCAP;
            u64 c0, c1, c2, c3, c4, c5;
            c0 = (lane       < cnt) ? cand[lane      ] : ~0ull;
            c1 = (lane + 32  < cnt) ? cand[lane + 32 ] : ~0ull;
            c2 = (lane + 64  < cnt) ? cand[lane + 64 ] : ~0ull;
            c3 = (lane + 96  < cnt) ? cand[lane + 96 ] : ~0ull;
            c4 = (lane + 128 < cnt) ? cand[lane + 128] : ~0ull;
            c5 = ~0ull;
            ce(c0,c1); ce(c2,c3); ce(c4,c5);
            ce(c0,c2); ce(c3,c5); ce(c1,c4);
            ce(c0,c1); ce(c2,c3); ce(c4,c5);
            ce(c1,c2); ce(c3,c4); ce(c2,c3);

            unsigned hdb = (unsigned)(c0 >> 32);
#pragma unroll 1
            for (int r = 0; r < KCAP; r++) {
                unsigned m = redux_min_u32(hdb);
                unsigned tied = __ballot_sync(FULLMASK, hdb == m);
                int src;
                if ((tied & (tied - 1u)) == 0u) {
                    src = __ffs(tied) - 1;
                } else {
                    unsigned lw = (hdb == m) ? (unsigned)c0 : 0xffffffffu;
                    unsigned mi = redux_min_u32(lw);
                    src = __ffs(__ballot_sync(FULLMASK, lw == mi)) - 1;
                }
                u64 win = __shfl_sync(FULLMASK, c0, src);
                if (lane == r) mykey = win;
                bool pop = (lane == src);
                c0 = pop ? c1 : c0;
                c1 = pop ? c2 : c1;
                c2 = pop ? c3 : c2;
                c3 = pop ? c4 : c3;
                c4 = pop ? c5 : c4;
                c5 = pop ? ~0ull : c5;
                hdb = (unsigned)(c0 >> 32);
            }
        }
        float seld2  = __uint_as_float((unsigned)(mykey >> 32));
        int   selidx = (int)(mykey & 0xffffffffu);
        if (lane >= nsel) { seld2 = 3.4e38f; selidx = 0; }

        bool v0 = (lane < nsel) && (seld2 <= R0SQ);
        int  c0cnt = __popc(__ballot_sync(FULLMASK, v0));
        float coeff = 0.0f;
        if (v0)          coeff += sw0v / (float)(c0cnt > 1 ? c0cnt : 1);
        if (lane < nsel) coeff += sw1v / (float)(nsel  > 1 ? nsel  : 1);

        const float* frowf = rnd + (size_t)(bix * NL + selidx) * H;
        asm volatile("prefetch.global.L1 [%0];" :: "l"(frowf));
        asm volatile("prefetch.global.L1 [%0];" :: "l"(frowf + 32));

        // ---- layer 0 ----
        float h0[64];
        {
            float2 yc = __ldg(latf2 + selidx);
            u64 yx2 = pk2(yc.x, yc.x), yy2 = pk2(yc.y, yc.y);
            u64 qx2 = pk2(qx, qx),     qy2 = pk2(qy, qy);
            const u64* w0r0 = (const u64*)(sm + OFF_WE0);
            const u64* w0r1 = (const u64*)(sm + OFF_WE0 + 64);
            const u64* w0r2 = (const u64*)(sm + OFF_WE0 + 128);
            const u64* w0r3 = (const u64*)(sm + OFF_WE0 + 192);
            const u64* b0p  = (const u64*)(sm + OFF_BE0);
#pragma unroll
            for (int jp = 0; jp < 32; jp++) {
                u64 t = b0p[jp];
                t = f2fma(yx2, w0r0[jp], t);
                t = f2fma(yy2, w0r1[jp], t);
                t = f2fma(qx2, w0r2[jp], t);
                t = f2fma(qy2, w0r3[jp], t);
                float a, b; upk2(t, a, b);
                h0[2*jp]   = gelu_f(a);
                h0[2*jp+1] = gelu_f(b);
            }
        }

        // ---- layer 1 (channel-tiled x2) ----
        float h1[64];
        {
            const ulonglong2* w1 = (const ulonglong2*)(sm + OFF_W1);
#pragma unroll
            for (int t = 0; t < 2; t++) {
                u64 a[16];
                const u64* b1p = (const u64*)(sm + OFF_BE1) + 8*t;
#pragma unroll
                for (int p = 0; p < 16; p++) a[p] = b1p[p];
#pragma unroll 4
                for (int i = 0; i < 64; i++) {
                    u64 hh = pk2(h0[i], h0[i]);
                    const ulonglong2* row = w1 + i*16 + t*8;
#pragma unroll
                    for (int j2 = 0; j2 < 8; j2++) {
                        ulonglong2 w = row[j2];
                        a[2*j2]   = f2fma(hh, w.x, a[2*j2]);
                        a[2*j2+1] = f2fma(hh, w.y, a[2*j2+1]);
                    }
                }
#pragma unroll
                for (int p = 0; p < 16; p++) {
                    float x, y; upk2(a[p], x, y);
                    h1[32*t + 2*p]   = gelu_f(x);
                    h1[32*t + 2*p+1] = gelu_f(y);
                }
            }
        }

        // ---- layer 2 + f(y)*coeff + butterfly reduce-scatter over neighbors ----
        u64 myd = 0;
        {
            u64 cc = pk2(coeff, coeff);
            const float4* frow = (const float4*)frowf;
            const ulonglong2* w2 = (const ulonglong2*)(sm + OFF_W2);
#pragma unroll
            for (int t = 0; t < 2; t++) {
                u64 a[16];
                const u64* b2p = (const u64*)(sm + OFF_BE2) + 8*t;
#pragma unroll
                for (int p = 0; p < 16; p++) a[p] = b2p[p];
#pragma unroll 4
                for (int i = 0; i < 64; i++) {
                    u64 hh = pk2(h1[i], h1[i]);
                    const ulonglong2* row = w2 + i*16 + t*8;
#pragma unroll
                    for (int j2 = 0; j2 < 8; j2++) {
                        ulonglong2 w = row[j2];
                        a[2*j2]   = f2fma(hh, w.x, a[2*j2]);
                        a[2*j2+1] = f2fma(hh, w.y, a[2*j2+1]);
                    }
                }
                // weight by f(y)*coeff (a[p] = channel pair (32t+2p, 32t+2p+1))
#pragma unroll
                for (int p2 = 0; p2 < 8; p2++) {
                    float4 f4 = __ldg(frow + 8*t + p2);
                    a[2*p2]   = f2mul(a[2*p2],   f2mul(pk2(f4.x, f4.y), cc));
                    a[2*p2+1] = f2mul(a[2*p2+1], f2mul(pk2(f4.z, f4.w), cc));
                }
                // butterfly reduce-scatter: 16 accs over 32 lanes, 5 stages.
                // After stage for lane-bit b, live accs have p-bit b == lane-bit b.
                {
                    bool k3 = (lane >> 3) & 1;
#pragma unroll
                    for (int j = 0; j < 8; j++) {
                        u64 sendv = k3 ? a[j] : a[j+8];
                        u64 recv  = __shfl_xor_sync(FULLMASK, sendv, 8);
                        a[j] = f2add(k3 ? a[j+8] : a[j], recv);
                    }
                    bool k2 = (lane >> 2) & 1;
#pragma unroll
                    for (int j = 0; j < 4; j++) {
                        u64 sendv = k2 ? a[j] : a[j+4];
                        u64 recv  = __shfl_xor_sync(FULLMASK, sendv, 4);
                        a[j] = f2add(k2 ? a[j+4] : a[j], recv);
                    }
                    bool k1 = (lane >> 1) & 1;
#pragma unroll
                    for (int j = 0; j < 2; j++) {
                        u64 sendv = k1 ? a[j] : a[j+2];
                        u64 recv  = __shfl_xor_sync(FULLMASK, sendv, 2);
                        a[j] = f2add(k1 ? a[j+2] : a[j], recv);
                    }
                    bool k0 = lane & 1;
                    {
                        u64 sendv = k0 ? a[0] : a[1];
                        u64 recv  = __shfl_xor_sync(FULLMASK, sendv, 1);
                        a[0] = f2add(k0 ? a[1] : a[0], recv);
                    }
                    // final: sum the two 16-lane halves
                    a[0] = f2add(a[0], __shfl_xor_sync(FULLMASK, a[0], 16));
                    // lane now owns channel pair p = (lane&15) + 16t
                    if ((lane >> 4) == t) myd = a[0];
                }
            }
        }
        // coalesced decoded store: lane l -> channels 2l, 2l+1
        ((u64*)g_dec)[(size_t)q * 32 + lane] = myd;
    }
}

// ======== projection kernel: decoded[64] -> gelu(PH=256) -> COUT=3 ========
static constexpr int PTHREADS = 128;
static constexpr int PGRID    = NB * NQ / PTHREADS;   // 256

// proj smem layout (floats)
static constexpr int POFF_WP0 = 0;          // 16384  [64][256]
static constexpr int POFF_BP0 = 16384;      // 256
static constexpr int POFF_WP1 = 16640;      // 768    [256][3]
static constexpr int POFF_BP1 = 17408;      // 3 (+1 pad)
static constexpr int PSMEM_FLOATS = 17412;
static constexpr int PSMEM_BYTES  = PSMEM_FLOATS * 4;   // 69648 B

__global__ void __launch_bounds__(PTHREADS)
proj_kernel(const float* __restrict__ wp0, const float* __restrict__ bp0,
            const float* __restrict__ wp1, const float* __restrict__ bp1,
            float* __restrict__ out)
{
    extern __shared__ float psm[];
    const int tid = threadIdx.x;
    for (int t = tid; t < H*PH;    t += PTHREADS) psm[POFF_WP0+t] = wp0[t];
    for (int t = tid; t < PH;      t += PTHREADS) psm[POFF_BP0+t] = bp0[t];
    for (int t = tid; t < PH*COUT; t += PTHREADS) psm[POFF_WP1+t] = wp1[t];
    if (tid < COUT) psm[POFF_BP1+tid] = bp1[tid];
    __syncthreads();

    const int row = blockIdx.x * PTHREADS + tid;

    // decoded row in registers
    float dec[64];
    {
        const float4* dp = (const float4*)(g_dec + (size_t)row * H);
#pragma unroll
        for (int i = 0; i < 16; i++) {
            float4 v = dp[i];
            dec[4*i+0] = v.x; dec[4*i+1] = v.y;
            dec[4*i+2] = v.z; dec[4*i+3] = v.w;
        }
    }

    float o0 = psm[POFF_BP1+0], o1 = psm[POFF_BP1+1], o2 = psm[POFF_BP1+2];

#pragma unroll 1
    for (int ch = 0; ch < 4; ch++) {           // 4 chunks of 64 hidden
        u64 a[32];
        {
            const u64* bp = (const u64*)(psm + POFF_BP0 + ch * 64);
#pragma unroll
            for (int p = 0; p < 32; p++) a[p] = bp[p];
        }
#pragma unroll 4
        for (int i = 0; i < 64; i++) {
            u64 dd = pk2(dec[i], dec[i]);
            const ulonglong2* wr =
                (const ulonglong2*)(psm + POFF_WP0 + (size_t)i * PH + ch * 64);
#pragma unroll
            for (int j2 = 0; j2 < 16; j2++) {
                ulonglong2 w = wr[j2];          // LDS.128 broadcast
                a[2*j2]   = f2fma(dd, w.x, a[2*j2]);
                a[2*j2+1] = f2fma(dd, w.y, a[2*j2+1]);
            }
        }
#pragma unroll
        for (int p = 0; p < 32; p++) {
            float x, y; upk2(a[p], x, y);
            float g0 = gelu_f(x), g1 = gelu_f(y);
            int jj = ch * 64 + 2 * p;
            o0 = fmaf(g0, psm[POFF_WP1 + jj*3 + 0], o0);
            o1 = fmaf(g0, psm[POFF_WP1 + jj*3 + 1], o1);
            o2 = fmaf(g0, psm[POFF_WP1 + jj*3 + 2], o2);
            o0 = fmaf(g1, psm[POFF_WP1 + jj*3 + 3], o0);
            o1 = fmaf(g1, psm[POFF_WP1 + jj*3 + 4], o1);
            o2 = fmaf(g1, psm[POFF_WP1 + jj*3 + 5], o2);
        }
    }

    out[row*3 + 0] = o0;
    out[row*3 + 1] = o1;
    out[row*3 + 2] = o2;
}

extern "C" void kernel_launch(void* const* d_in, const int* in_sizes, int n_in,
                              void* d_out, int out_size) {
    const float* lat  = (const float*)d_in[0];
    const float* rnd  = (const float*)d_in[1];
    const float* qry  = (const float*)d_in[2];
    const float* we0  = (const float*)d_in[3];
    const float* be0  = (const float*)d_in[4];
    const float* we1  = (const float*)d_in[5];
    const float* be1  = (const float*)d_in[6];
    const float* we2  = (const float*)d_in[7];
    const float* be2  = (const float*)d_in[8];
    const float* wsw0 = (const float*)d_in[9];
    const float* bsw0 = (const float*)d_in[10];
    const float* wsw1 = (const float*)d_in[11];
    const float* bsw1 = (const float*)d_in[12];
    const float* wp0  = (const float*)d_in[13];
    const float* bp0  = (const float*)d_in[14];
    const float* wp1  = (const float*)d_in[15];
    const float* bp1  = (const float*)d_in[16];
    float* out = (float*)d_out;

    cudaFuncSetAttribute(magno_kernel, cudaFuncAttributeMaxDynamicSharedMemorySize, SMEM_BYTES);
    cudaFuncSetAttribute(proj_kernel,  cudaFuncAttributeMaxDynamicSharedMemorySize, PSMEM_BYTES);
    magno_kernel<<<NBLOCK, THREADS, SMEM_BYTES>>>(
        lat, rnd, qry, we0, be0, we1, be1, we2, be2,
        wsw0, bsw0, wsw1, bsw1);
    proj_kernel<<<PGRID, PTHREADS, PSMEM_BYTES>>>(wp0, bp0, wp1, bp1, out);
}